// round 5
// baseline (speedup 1.0000x reference)
#include <cuda_runtime.h>
#include <math.h>
#include <stdint.h>

#define TT 8192
#define DD 256
#define FF 1024
#define EE 32
#define KK 4

#define TM 64   // tokens per block tile
#define FC 64   // ffn chunk

// ---------------- scratch (static device globals; no allocation) ----------------
__device__ int   g_counts[EE];
__device__ int   g_offsets[EE + 1];
__device__ float g_probs_sum[EE];
__device__ int   g_as_e[TT * KK];
__device__ int   g_as_pos[TT * KK];
__device__ float g_as_w[TT * KK];
__device__ int   g_list_tok[TT * KK];
__device__ float g_list_w[TT * KK];

// ---------------- init ----------------
__global__ void init_kernel()
{
    int i = threadIdx.x;
    if (i < EE) { g_counts[i] = 0; g_probs_sum[i] = 0.f; }
}

// ---------------- router: 8 warps/block, 1 token/warp ----------------
__global__ __launch_bounds__(256) void router_kernel(const float* __restrict__ x,
                                                     const float* __restrict__ rw)
{
    __shared__ float rw_s[EE * 257];   // padded: bank = (e+d)&31, conflict-free
    __shared__ float xsh[8 * 260];
    __shared__ float pacc[EE];

    const int tid  = threadIdx.x;
    const int lane = tid & 31;
    const int warp = tid >> 5;

    for (int i = tid; i < EE * DD; i += 256) {
        int e = i >> 8, d = i & 255;
        rw_s[e * 257 + d] = rw[i];
    }
    if (tid < EE) pacc[tid] = 0.f;
    __syncthreads();

    const int t = blockIdx.x * 8 + warp;
    {
        const float4* xr = (const float4*)(x + (size_t)t * DD);
        float4 a = xr[lane * 2];
        float4 b = xr[lane * 2 + 1];
        *(float4*)&xsh[warp * 260 + lane * 8]     = a;
        *(float4*)&xsh[warp * 260 + lane * 8 + 4] = b;
    }
    __syncwarp();

    // lane = expert
    float acc = 0.f;
    const float* xrow  = &xsh[warp * 260];
    const float* rwrow = &rw_s[lane * 257];
#pragma unroll 8
    for (int d = 0; d < DD; d++) acc = fmaf(xrow[d], rwrow[d], acc);
    const float logit = acc;

    // full softmax -> probs accumulation (for aux loss)
    float m = logit;
#pragma unroll
    for (int o = 16; o; o >>= 1) m = fmaxf(m, __shfl_xor_sync(0xffffffffu, m, o));
    float p = expf(logit - m);
    float s = p;
#pragma unroll
    for (int o = 16; o; o >>= 1) s += __shfl_xor_sync(0xffffffffu, s, o);
    atomicAdd(&pacc[lane], p / s);

    // top-4 (lower index wins ties, matching lax.top_k)
    float lv = logit;
    float vals[KK]; int idxs[KK];
#pragma unroll
    for (int k = 0; k < KK; k++) {
        float v = lv; int id = lane;
#pragma unroll
        for (int o = 16; o; o >>= 1) {
            float v2 = __shfl_xor_sync(0xffffffffu, v, o);
            int   i2 = __shfl_xor_sync(0xffffffffu, id, o);
            if (v2 > v || (v2 == v && i2 < id)) { v = v2; id = i2; }
        }
        vals[k] = v; idxs[k] = id;
        if (lane == id) lv = __int_as_float(0xff800000);  // -inf
    }

    // softmax over top-4 (vals[0] is max)
    float ws[KK]; float sum = 0.f;
#pragma unroll
    for (int k = 0; k < KK; k++) { ws[k] = expf(vals[k] - vals[0]); sum += ws[k]; }
    const float inv = 1.f / sum;

    if (lane == 0) {
#pragma unroll
        for (int k = 0; k < KK; k++) {
            int e   = idxs[k];
            int pos = atomicAdd(&g_counts[e], 1);
            int a   = t * KK + k;
            g_as_e[a] = e; g_as_pos[a] = pos; g_as_w[a] = ws[k] * inv;
        }
    }
    __syncthreads();
    if (tid < EE) atomicAdd(&g_probs_sum[tid], pacc[tid]);
}

// ---------------- scan offsets + aux loss ----------------
__global__ void scan_aux_kernel(float* __restrict__ out, int out_size)
{
    const int tid = threadIdx.x;   // 32 threads
    int c = g_counts[tid];
    int v = c;
#pragma unroll
    for (int o = 1; o < 32; o <<= 1) {
        int n = __shfl_up_sync(0xffffffffu, v, o);
        if (tid >= o) v += n;
    }
    g_offsets[tid] = v - c;
    if (tid == 31) g_offsets[EE] = v;

    const float invT = 1.f / (float)TT;
    float part = ((float)c * invT) * (g_probs_sum[tid] * invT);
#pragma unroll
    for (int o = 16; o; o >>= 1) part += __shfl_xor_sync(0xffffffffu, part, o);
    if (tid == 0 && out_size > TT * DD) out[(size_t)TT * DD] = (float)EE * part;
}

// ---------------- build per-expert token lists ----------------
__global__ void fill_kernel()
{
    int i = blockIdx.x * blockDim.x + threadIdx.x;
    if (i < TT * KK) {
        int e    = g_as_e[i];
        int slot = g_offsets[e] + g_as_pos[i];
        g_list_tok[slot] = i >> 2;
        g_list_w[slot]   = g_as_w[i];
    }
}

// ---------------- fused expert FFN (SwiGLU) ----------------
// shared layout (floats):
constexpr int XS_F = 256 * 68;     // XsT[d][r], padded stride 68
constexpr int HS_F = 64 * 68;      // HsT[f][r]
constexpr int WD_F = 256 * 65;     // Wd[dcol][fl], stride 65 (union with WGT/WUT staging)
constexpr int SMEM_FLOATS = XS_F + HS_F + WD_F + 64 + 64;
constexpr int SMEM_BYTES  = SMEM_FLOATS * 4;   // 154112 B

__global__ __launch_bounds__(256, 1)
void moe_expert_kernel(const float* __restrict__ x,
                       const float* __restrict__ w_gate,
                       const float* __restrict__ w_up,
                       const float* __restrict__ w_down,
                       float* __restrict__ out)
{
    extern __shared__ float sm[];
    float* XsT = sm;                  // [256][68]
    float* HsT = XsT + XS_F;          // [64][68]
    float* WD  = HsT + HS_F;          // [256][65]   (union)
    float* WGT = WD;                  // [32][68]
    float* WUT = WD + 32 * 68;        // [32][68]
    int*   toks = (int*)(WD + WD_F);
    float* wsh  = (float*)(toks + TM);

    const int e     = blockIdx.y;
    const int base  = g_offsets[e];
    const int count = g_offsets[e + 1] - base;
    const int m0    = blockIdx.x * TM;
    if (m0 >= count) return;

    const int tid  = threadIdx.x;
    const int tx   = tid & 15;
    const int ty   = tid >> 4;
    const int lane = tid & 31;
    const int warp = tid >> 5;

    if (tid < TM) {
        int r = m0 + tid;
        if (r < count) { toks[tid] = g_list_tok[base + r]; wsh[tid] = g_list_w[base + r]; }
        else           { toks[tid] = -1;                   wsh[tid] = 0.f; }
    }
    __syncthreads();

    // load X tile transposed into shared
    for (int r = warp; r < TM; r += 8) {
        int t = toks[r];
        float4 a = make_float4(0.f, 0.f, 0.f, 0.f), b = a;
        if (t >= 0) {
            const float4* xr = (const float4*)(x + (size_t)t * DD);
            a = xr[lane * 2]; b = xr[lane * 2 + 1];
        }
        int d = lane * 8;
        XsT[(d + 0) * 68 + r] = a.x; XsT[(d + 1) * 68 + r] = a.y;
        XsT[(d + 2) * 68 + r] = a.z; XsT[(d + 3) * 68 + r] = a.w;
        XsT[(d + 4) * 68 + r] = b.x; XsT[(d + 5) * 68 + r] = b.y;
        XsT[(d + 6) * 68 + r] = b.z; XsT[(d + 7) * 68 + r] = b.w;
    }

    const float* wg_e = w_gate + (size_t)e * FF * DD;
    const float* wu_e = w_up   + (size_t)e * FF * DD;
    const float* wd_e = w_down + (size_t)e * DD * FF;

    float acc[4][16];
#pragma unroll
    for (int i = 0; i < 4; i++)
#pragma unroll
        for (int j = 0; j < 16; j++) acc[i][j] = 0.f;

    for (int f0 = 0; f0 < FF; f0 += FC) {
        float G[4][4], U[4][4];
#pragma unroll
        for (int i = 0; i < 4; i++)
#pragma unroll
            for (int j = 0; j < 4; j++) { G[i][j] = 0.f; U[i][j] = 0.f; }

        // ---- GEMM1: G = X Wg^T, U = X Wu^T over K=D=256 in 32-slices ----
        for (int k0 = 0; k0 < DD; k0 += 32) {
            __syncthreads();   // protects WD/WGT/WUT union + XsT visibility
#pragma unroll
            for (int i = 0; i < 2; i++) {
                int idx4 = tid + i * 256;        // 512 float4 per matrix
                int fl = idx4 >> 3;
                int d4 = idx4 & 7;
                const float4 g4 = *(const float4*)(wg_e + (size_t)(f0 + fl) * DD + k0 + d4 * 4);
                const float4 u4 = *(const float4*)(wu_e + (size_t)(f0 + fl) * DD + k0 + d4 * 4);
                int dl = d4 * 4;
                WGT[(dl + 0) * 68 + fl] = g4.x; WGT[(dl + 1) * 68 + fl] = g4.y;
                WGT[(dl + 2) * 68 + fl] = g4.z; WGT[(dl + 3) * 68 + fl] = g4.w;
                WUT[(dl + 0) * 68 + fl] = u4.x; WUT[(dl + 1) * 68 + fl] = u4.y;
                WUT[(dl + 2) * 68 + fl] = u4.z; WUT[(dl + 3) * 68 + fl] = u4.w;
            }
            __syncthreads();
#pragma unroll 8
            for (int kk = 0; kk < 32; kk++) {
                const float4 xr4 = *(const float4*)&XsT[(k0 + kk) * 68 + 4 * ty];
                const float4 g4  = *(const float4*)&WGT[kk * 68 + 4 * tx];
                const float4 u4  = *(const float4*)&WUT[kk * 68 + 4 * tx];
                const float xa[4] = {xr4.x, xr4.y, xr4.z, xr4.w};
                const float ga[4] = {g4.x, g4.y, g4.z, g4.w};
                const float ua[4] = {u4.x, u4.y, u4.z, u4.w};
#pragma unroll
                for (int i = 0; i < 4; i++)
#pragma unroll
                    for (int j = 0; j < 4; j++) {
                        G[i][j] = fmaf(xa[i], ga[j], G[i][j]);
                        U[i][j] = fmaf(xa[i], ua[j], U[i][j]);
                    }
            }
        }

        // ---- h = silu(G) * U -> HsT[f][r] ----
#pragma unroll
        for (int c = 0; c < 4; c++)
#pragma unroll
            for (int i = 0; i < 4; i++) {
                float g = G[i][c];
                float h = (g / (1.f + expf(-g))) * U[i][c];
                HsT[(4 * tx + c) * 68 + 4 * ty + i] = h;
            }
        __syncthreads();   // all GEMM1 reads + HsT writes complete

        // ---- stage Wd chunk: WD[dcol][fl] (stride 65, conflict-free r/w) ----
#pragma unroll 4
        for (int i = 0; i < 64; i++) {
            int idx  = tid + i * 256;
            int dcol = idx >> 6;
            int fl   = idx & 63;
            WD[dcol * 65 + fl] = wd_e[(size_t)dcol * FF + f0 + fl];
        }
        __syncthreads();

        // ---- GEMM2: acc += h Wd^T ----
#pragma unroll 4
        for (int kk = 0; kk < FC; kk++) {
            const float4 h4 = *(const float4*)&HsT[kk * 68 + 4 * ty];
            const float hv[4] = {h4.x, h4.y, h4.z, h4.w};
            float wv[16];
#pragma unroll
            for (int j = 0; j < 16; j++) wv[j] = WD[(tx + 16 * j) * 65 + kk];
#pragma unroll
            for (int i = 0; i < 4; i++)
#pragma unroll
                for (int j = 0; j < 16; j++)
                    acc[i][j] = fmaf(hv[i], wv[j], acc[i][j]);
        }
    }

    // ---- weighted scatter-add ----
#pragma unroll
    for (int i = 0; i < 4; i++) {
        int r = 4 * ty + i;
        int t = toks[r];
        if (t < 0) continue;
        float w = wsh[r];
        float* orow = out + (size_t)t * DD;
#pragma unroll
        for (int j = 0; j < 16; j++)
            atomicAdd(&orow[tx + 16 * j], w * acc[i][j]);
    }
}

// ---------------- launch ----------------
extern "C" void kernel_launch(void* const* d_in, const int* in_sizes, int n_in,
                              void* d_out, int out_size)
{
    const float* x  = (const float*)d_in[0];
    const float* rw = (const float*)d_in[1];
    const float* wg = (const float*)d_in[2];
    const float* wu = (const float*)d_in[3];
    const float* wd = (const float*)d_in[4];
    float* out = (float*)d_out;

    cudaMemsetAsync(d_out, 0, (size_t)out_size * sizeof(float));
    init_kernel<<<1, 32>>>();
    router_kernel<<<TT / 8, 256>>>(x, rw);
    scan_aux_kernel<<<1, 32>>>(out, out_size);
    fill_kernel<<<(TT * KK + 255) / 256, 256>>>();

    cudaFuncSetAttribute(moe_expert_kernel,
                         cudaFuncAttributeMaxDynamicSharedMemorySize, SMEM_BYTES);
    dim3 grid(TT / TM, EE);   // 128 tiles x 32 experts; tiles beyond count exit early
    moe_expert_kernel<<<grid, 256, SMEM_BYTES>>>(x, wg, wu, wd, out);
}

// round 9
// speedup vs baseline: 3.3920x; 3.3920x over previous
#include <cuda_runtime.h>
#include <math.h>
#include <stdint.h>

#define TT 8192
#define DD 256
#define FF 1024
#define EE 32
#define KK 4
#define TM 128            // tokens per tile (MMA M)
#define FC 64             // ffn chunk
#define NCH (FF / FC)     // 16

// ---------------- scratch globals ----------------
__device__ int   g_counts[EE];
__device__ int   g_offsets[EE + 1];
__device__ float g_probs_sum[EE];
__device__ int   g_as_e[TT * KK];
__device__ int   g_as_pos[TT * KK];
__device__ float g_as_w[TT * KK];
__device__ int   g_list_tok[TT * KK];
__device__ float g_list_w[TT * KK];
__device__ int   g_slot[TT * KK];
__device__ int   g_tile_e[2048];
__device__ int   g_tile_m0[2048];
__device__ int   g_ntiles;
__device__ float g_scratch[(size_t)TT * KK * DD];   // 32 MB partials

// ---------------- PTX helpers ----------------
__device__ __forceinline__ uint32_t f2tf(float f) {
    uint32_t u;
    asm("cvt.rna.tf32.f32 %0, %1;" : "=r"(u) : "f"(f));
    return u;
}
__device__ __forceinline__ void mma8(float* c, const uint32_t* a, uint32_t b0, uint32_t b1) {
    asm("mma.sync.aligned.m16n8k8.row.col.f32.tf32.tf32.f32 "
        "{%0,%1,%2,%3},{%4,%5,%6,%7},{%8,%9},{%0,%1,%2,%3};"
        : "+f"(c[0]), "+f"(c[1]), "+f"(c[2]), "+f"(c[3])
        : "r"(a[0]), "r"(a[1]), "r"(a[2]), "r"(a[3]), "r"(b0), "r"(b1));
}
__device__ __forceinline__ void cp16(uint32_t dst, const void* src) {
    asm volatile("cp.async.cg.shared.global [%0], [%1], 16;" :: "r"(dst), "l"(src));
}
#define CP_COMMIT() asm volatile("cp.async.commit_group;" ::: "memory")
#define CP_WAIT0()  asm volatile("cp.async.wait_group 0;" ::: "memory")
#define CP_WAIT1()  asm volatile("cp.async.wait_group 1;" ::: "memory")

__device__ __forceinline__ uint32_t smem_u32(const void* p) {
    uint32_t a;
    asm("{ .reg .u64 t; cvta.to.shared.u64 t, %1; cvt.u32.u64 %0, t; }" : "=r"(a) : "l"(p));
    return a;
}

// FFMA-only sigmoid (no MUFU): sigma(g) = 1/(1+2^(-g*log2 e))
__device__ __forceinline__ float fast_sigmoid(float x) {
    float t = -1.442695041f * x;
    float fn = rintf(t);
    int   n  = (int)fn;
    float f  = t - fn;                               // [-0.5, 0.5]
    float p = 0.0013333558f;
    p = fmaf(p, f, 0.0096181291f);
    p = fmaf(p, f, 0.0555041087f);
    p = fmaf(p, f, 0.2402265069f);
    p = fmaf(p, f, 0.6931471806f);
    p = fmaf(p, f, 1.0f);
    float e = __int_as_float(__float_as_int(p) + (n << 23));   // e^-x
    float d = 1.0f + e;
    float r = __int_as_float(0x7EF311C3 - __float_as_int(d));
    r = r * (2.0f - d * r);
    r = r * (2.0f - d * r);
    r = r * (2.0f - d * r);
    return r;
}

// ---------------- init ----------------
__global__ void init_kernel()
{
    int i = threadIdx.x;
    if (i < EE) { g_counts[i] = 0; g_probs_sum[i] = 0.f; }
}

// ---------------- router (known-good from R3) ----------------
__global__ __launch_bounds__(256) void router_kernel(const float* __restrict__ x,
                                                     const float* __restrict__ rw)
{
    __shared__ float rw_s[EE * 257];
    __shared__ float xsh[8 * 260];
    __shared__ float pacc[EE];

    const int tid  = threadIdx.x;
    const int lane = tid & 31;
    const int warp = tid >> 5;

    for (int i = tid; i < EE * DD; i += 256) {
        int e = i >> 8, d = i & 255;
        rw_s[e * 257 + d] = rw[i];
    }
    if (tid < EE) pacc[tid] = 0.f;
    __syncthreads();

    const int t = blockIdx.x * 8 + warp;
    {
        const float4* xr = (const float4*)(x + (size_t)t * DD);
        float4 a = xr[lane * 2];
        float4 b = xr[lane * 2 + 1];
        *(float4*)&xsh[warp * 260 + lane * 8]     = a;
        *(float4*)&xsh[warp * 260 + lane * 8 + 4] = b;
    }
    __syncwarp();

    float acc = 0.f;
    const float* xrow  = &xsh[warp * 260];
    const float* rwrow = &rw_s[lane * 257];
#pragma unroll 8
    for (int d = 0; d < DD; d++) acc = fmaf(xrow[d], rwrow[d], acc);
    const float logit = acc;

    float m = logit;
#pragma unroll
    for (int o = 16; o; o >>= 1) m = fmaxf(m, __shfl_xor_sync(0xffffffffu, m, o));
    float p = expf(logit - m);
    float s = p;
#pragma unroll
    for (int o = 16; o; o >>= 1) s += __shfl_xor_sync(0xffffffffu, s, o);
    atomicAdd(&pacc[lane], p / s);

    float lv = logit;
    float vals[KK]; int idxs[KK];
#pragma unroll
    for (int k = 0; k < KK; k++) {
        float v = lv; int id = lane;
#pragma unroll
        for (int o = 16; o; o >>= 1) {
            float v2 = __shfl_xor_sync(0xffffffffu, v, o);
            int   i2 = __shfl_xor_sync(0xffffffffu, id, o);
            if (v2 > v || (v2 == v && i2 < id)) { v = v2; id = i2; }
        }
        vals[k] = v; idxs[k] = id;
        if (lane == id) lv = __int_as_float(0xff800000);
    }

    float ws[KK]; float sum = 0.f;
#pragma unroll
    for (int k = 0; k < KK; k++) { ws[k] = expf(vals[k] - vals[0]); sum += ws[k]; }
    const float inv = 1.f / sum;

    if (lane == 0) {
#pragma unroll
        for (int k = 0; k < KK; k++) {
            int e   = idxs[k];
            int pos = atomicAdd(&g_counts[e], 1);
            int a   = t * KK + k;
            g_as_e[a] = e; g_as_pos[a] = pos; g_as_w[a] = ws[k] * inv;
        }
    }
    __syncthreads();
    if (tid < EE) atomicAdd(&g_probs_sum[tid], pacc[tid]);
}

// ---------------- scan offsets + aux loss + tile list ----------------
__global__ void scan_aux_kernel(float* __restrict__ out, int out_size)
{
    const int tid = threadIdx.x;   // 32 threads
    int c = g_counts[tid];
    int v = c;
#pragma unroll
    for (int o = 1; o < 32; o <<= 1) {
        int n = __shfl_up_sync(0xffffffffu, v, o);
        if (tid >= o) v += n;
    }
    g_offsets[tid] = v - c;
    if (tid == 31) g_offsets[EE] = v;

    int nt = (c + TM - 1) / TM;
    int tv = nt;
#pragma unroll
    for (int o = 1; o < 32; o <<= 1) {
        int n = __shfl_up_sync(0xffffffffu, tv, o);
        if (tid >= o) tv += n;
    }
    int tb = tv - nt;
    for (int j = 0; j < nt; j++) { g_tile_e[tb + j] = tid; g_tile_m0[tb + j] = j * TM; }
    if (tid == 31) g_ntiles = tv;

    const float invT = 1.f / (float)TT;
    float part = ((float)c * invT) * (g_probs_sum[tid] * invT);
#pragma unroll
    for (int o = 16; o; o >>= 1) part += __shfl_xor_sync(0xffffffffu, part, o);
    if (tid == 0 && out_size > TT * DD) out[(size_t)TT * DD] = (float)EE * part;
}

// ---------------- per-expert token lists + slot map ----------------
__global__ void fill_kernel()
{
    int i = blockIdx.x * blockDim.x + threadIdx.x;
    if (i < TT * KK) {
        int e    = g_as_e[i];
        int slot = g_offsets[e] + g_as_pos[i];
        g_list_tok[slot] = i >> 2;
        g_list_w[slot]   = g_as_w[i];
        g_slot[i]        = slot;
    }
}

// ---------------- mma.sync tf32 fused expert FFN ----------------
// SMEM layout (float offsets):
//   Xs  [128][260]           @ 0       (33280 f)
//   WS  [2][64][36]          @ 33280   (4608 f)   weight k-slices, double buffered
//   hS  [128][68]            @ 37888   (8704 f)   G raw, then h (tf32-rounded)
//   WdS [2][64][68]          @ 46592   (8704 f)   Wd quarters, double buffered
//   toks[128], wsh[128]      @ 55296
constexpr int OFF_WS  = 33280;
constexpr int OFF_H   = 37888;
constexpr int OFF_WD  = 46592;
constexpr int OFF_TOK = 55296;
constexpr int OFF_WSH = 55424;
constexpr int EXP_SMEM = 55552 * 4;   // 222208 B

__global__ __launch_bounds__(256, 1)
void moe_mma_kernel(const float* __restrict__ x,
                    const float* __restrict__ w_gate,
                    const float* __restrict__ w_up,
                    const float* __restrict__ w_down)
{
    extern __shared__ float sm[];
    float* Xs  = sm;
    float* WS  = sm + OFF_WS;
    float* hS  = sm + OFF_H;
    float* WdS = sm + OFF_WD;
    int*   toks = (int*)(sm + OFF_TOK);
    float* wsh  = sm + OFF_WSH;

    const uint32_t ws_b = smem_u32(WS);
    const uint32_t wd_b = smem_u32(WdS);

    const int tid  = threadIdx.x;
    const int lane = tid & 31;
    const int warp = tid >> 5;
    const int lq   = lane & 3;        // quad index  (k within frag)
    const int lh   = lane >> 2;       // row/col within frag
    const int wm   = warp & 3;        // M tile (32 rows each)
    const int wn   = warp >> 2;       // N tile (32 cols each)
    const int rowA = wm * 32 + lh;    // A-frag base row
    const int fA   = wn * 32;         // phase-A f base (local in chunk)

    const int ntiles = g_ntiles;

    for (int tile = blockIdx.x; tile < ntiles; tile += gridDim.x) {
        const int e     = g_tile_e[tile];
        const int m0    = g_tile_m0[tile];
        const int base  = g_offsets[e];
        const int count = g_offsets[e + 1] - base;

        if (tid < TM) {
            int r = m0 + tid;
            bool v = r < count;
            toks[tid] = v ? g_list_tok[base + r] : -1;
            wsh[tid]  = v ? g_list_w[base + r] : 0.f;
        }
        __syncthreads();

        // ---- stage X (tf32-rounded) ----
#pragma unroll 8
        for (int j = 0; j < 32; j++) {
            int idx = tid + j * 256;
            int r = idx >> 6, c4 = (idx & 63) * 4;
            int t = toks[r];
            float4 v = make_float4(0.f, 0.f, 0.f, 0.f);
            if (t >= 0) v = *(const float4*)(x + (size_t)t * DD + c4);
            float4 w;
            w.x = __uint_as_float(f2tf(v.x));
            w.y = __uint_as_float(f2tf(v.y));
            w.z = __uint_as_float(f2tf(v.z));
            w.w = __uint_as_float(f2tf(v.w));
            *(float4*)&Xs[r * 260 + c4] = w;
        }

        const float* wg_e = w_gate + (size_t)e * FF * DD;
        const float* wu_e = w_up   + (size_t)e * FF * DD;
        const float* wd_e = w_down + (size_t)e * DD * FF;

        float acc[4][2][4][4];
#pragma unroll
        for (int q = 0; q < 4; q++)
#pragma unroll
            for (int mt = 0; mt < 2; mt++)
#pragma unroll
                for (int nt = 0; nt < 4; nt++)
#pragma unroll
                    for (int r = 0; r < 4; r++) acc[q][mt][nt][r] = 0.f;

        for (int c = 0; c < NCH; c++) {
            const int f0 = c * FC;

            // ======== Phase A: G pass (mat 0) then U pass (mat 1) ========
#pragma unroll 1
            for (int mat = 0; mat < 2; mat++) {
                const float* wsrc = mat ? wu_e : wg_e;
                float cA[2][4][4];
#pragma unroll
                for (int mt = 0; mt < 2; mt++)
#pragma unroll
                    for (int nt = 0; nt < 4; nt++)
#pragma unroll
                        for (int r = 0; r < 4; r++) cA[mt][nt][r] = 0.f;

                __syncthreads();   // WS free (prev use done), X visible
                // prologue: slice 0 -> buf 0
                {
#pragma unroll
                    for (int j = 0; j < 2; j++) {
                        int idx = tid + j * 256;
                        int f = idx >> 3, d4 = idx & 7;
                        cp16(ws_b + f * 144 + d4 * 16,
                             wsrc + (size_t)(f0 + f) * DD + d4 * 4);
                    }
                    CP_COMMIT();
                }
#pragma unroll 1
                for (int ks = 0; ks < 8; ks++) {
                    if (ks < 7) {
                        int d0n = (ks + 1) * 32;
                        uint32_t bb = ws_b + ((ks + 1) & 1) * 9216;
#pragma unroll
                        for (int j = 0; j < 2; j++) {
                            int idx = tid + j * 256;
                            int f = idx >> 3, d4 = idx & 7;
                            cp16(bb + f * 144 + d4 * 16,
                                 wsrc + (size_t)(f0 + f) * DD + d0n + d4 * 4);
                        }
                        CP_COMMIT();
                        CP_WAIT1();
                    } else {
                        CP_WAIT0();
                    }
                    __syncthreads();
                    const float* WSb = WS + (ks & 1) * 2304;
                    const int d0 = ks * 32;
#pragma unroll
                    for (int kk = 0; kk < 4; kk++) {
                        const int colX = d0 + kk * 8 + lq;
                        const int colW = kk * 8 + lq;
                        uint32_t a[2][4];
#pragma unroll
                        for (int mt = 0; mt < 2; mt++) {
                            int r = rowA + mt * 16;
                            a[mt][0] = __float_as_uint(Xs[r * 260 + colX]);
                            a[mt][1] = __float_as_uint(Xs[(r + 8) * 260 + colX]);
                            a[mt][2] = __float_as_uint(Xs[r * 260 + colX + 4]);
                            a[mt][3] = __float_as_uint(Xs[(r + 8) * 260 + colX + 4]);
                        }
#pragma unroll
                        for (int nt = 0; nt < 4; nt++) {
                            int fr = fA + nt * 8 + lh;
                            uint32_t b0 = f2tf(WSb[fr * 36 + colW]);
                            uint32_t b1 = f2tf(WSb[fr * 36 + colW + 4]);
                            mma8(cA[0][nt], a[0], b0, b1);
                            mma8(cA[1][nt], a[1], b0, b1);
                        }
                    }
                    __syncthreads();   // all reads of this buf done before reuse
                }

                if (mat == 0) {
                    // stash raw G into hS
#pragma unroll
                    for (int mt = 0; mt < 2; mt++)
#pragma unroll
                        for (int nt = 0; nt < 4; nt++) {
                            int row = rowA + mt * 16;
                            int col = fA + nt * 8 + 2 * lq;
                            *(float2*)&hS[row * 68 + col] =
                                make_float2(cA[mt][nt][0], cA[mt][nt][1]);
                            *(float2*)&hS[(row + 8) * 68 + col] =
                                make_float2(cA[mt][nt][2], cA[mt][nt][3]);
                        }
                } else {
                    // h = silu(G) * U, tf32-rounded, back into hS
#pragma unroll
                    for (int mt = 0; mt < 2; mt++)
#pragma unroll
                        for (int nt = 0; nt < 4; nt++) {
                            int row = rowA + mt * 16;
                            int col = fA + nt * 8 + 2 * lq;
#pragma unroll
                            for (int hf = 0; hf < 2; hf++) {
                                int rr = row + hf * 8;
                                float2 g2 = *(float2*)&hS[rr * 68 + col];
                                float h0 = g2.x * fast_sigmoid(g2.x) * cA[mt][nt][hf * 2 + 0];
                                float h1 = g2.y * fast_sigmoid(g2.y) * cA[mt][nt][hf * 2 + 1];
                                float2 o2;
                                o2.x = __uint_as_float(f2tf(h0));
                                o2.y = __uint_as_float(f2tf(h1));
                                *(float2*)&hS[rr * 68 + col] = o2;
                            }
                        }
                }
            }

            // ======== Phase B: out += h @ Wd^T  (4 quarters of D) ========
            __syncthreads();   // h visible to all; WdS free from prev chunk
            // prologue: quarter 0 -> buf 0
            {
#pragma unroll
                for (int j = 0; j < 4; j++) {
                    int idx = tid + j * 256;
                    int d = idx >> 4, f4 = idx & 15;
                    cp16(wd_b + d * 272 + f4 * 16,
                         wd_e + (size_t)d * FF + f0 + f4 * 4);
                }
                CP_COMMIT();
            }
#pragma unroll 1
            for (int q = 0; q < 4; q++) {
                if (q < 3) {
                    uint32_t bb = wd_b + ((q + 1) & 1) * 17408;
                    int dbase = (q + 1) * 64;
#pragma unroll
                    for (int j = 0; j < 4; j++) {
                        int idx = tid + j * 256;
                        int d = idx >> 4, f4 = idx & 15;
                        cp16(bb + d * 272 + f4 * 16,
                             wd_e + (size_t)(dbase + d) * FF + f0 + f4 * 4);
                    }
                    CP_COMMIT();
                    CP_WAIT1();
                } else {
                    CP_WAIT0();
                }
                __syncthreads();
                const float* WDb = WdS + (q & 1) * 4352;
#pragma unroll
                for (int kk = 0; kk < 8; kk++) {
                    const int kf = kk * 8 + lq;
                    uint32_t a[2][4];
#pragma unroll
                    for (int mt = 0; mt < 2; mt++) {
                        int r = rowA + mt * 16;
                        a[mt][0] = __float_as_uint(hS[r * 68 + kf]);
                        a[mt][1] = __float_as_uint(hS[(r + 8) * 68 + kf]);
                        a[mt][2] = __float_as_uint(hS[r * 68 + kf + 4]);
                        a[mt][3] = __float_as_uint(hS[(r + 8) * 68 + kf + 4]);
                    }
#pragma unroll
                    for (int nt = 0; nt < 4; nt++) {
                        int dn = wn * 32 + nt * 8 + lh;
                        uint32_t b0 = f2tf(WDb[dn * 68 + kf]);
                        uint32_t b1 = f2tf(WDb[dn * 68 + kf + 4]);
                        mma8(acc[q][0][nt], a[0], b0, b1);
                        mma8(acc[q][1][nt], a[1], b0, b1);
                    }
                }
                __syncthreads();   // buf free for next-next quarter
            }
        }

        // ---- epilogue: weighted write to scratch ----
#pragma unroll
        for (int q = 0; q < 4; q++)
#pragma unroll
            for (int mt = 0; mt < 2; mt++)
#pragma unroll
                for (int hf = 0; hf < 2; hf++) {
                    int tr = rowA + mt * 16 + hf * 8;
                    if (m0 + tr < count) {
                        float w = wsh[tr];
                        float* dst = g_scratch + (size_t)(base + m0 + tr) * DD
                                   + q * 64 + wn * 32 + 2 * lq;
#pragma unroll
                        for (int nt = 0; nt < 4; nt++) {
                            float2 v;
                            v.x = acc[q][mt][nt][hf * 2 + 0] * w;
                            v.y = acc[q][mt][nt][hf * 2 + 1] * w;
                            *(float2*)(dst + nt * 8) = v;
                        }
                    }
                }
        __syncthreads();   // protect toks/wsh/Xs before next tile
    }
}

// ---------------- combine: out[t] = sum of token's 4 weighted slots ----------------
__global__ __launch_bounds__(256) void combine_kernel(float* __restrict__ out)
{
    int idx = blockIdx.x * 256 + threadIdx.x;     // TT*64 float4 items
    int t = idx >> 6, q = (idx & 63) * 4;
    const int* sl = g_slot + t * 4;
    float4 a = *(const float4*)(g_scratch + (size_t)sl[0] * DD + q);
    float4 b = *(const float4*)(g_scratch + (size_t)sl[1] * DD + q);
    float4 c = *(const float4*)(g_scratch + (size_t)sl[2] * DD + q);
    float4 d = *(const float4*)(g_scratch + (size_t)sl[3] * DD + q);
    float4 r;
    r.x = a.x + b.x + c.x + d.x;
    r.y = a.y + b.y + c.y + d.y;
    r.z = a.z + b.z + c.z + d.z;
    r.w = a.w + b.w + c.w + d.w;
    *(float4*)(out + (size_t)t * DD + q) = r;
}

// ---------------- launch ----------------
extern "C" void kernel_launch(void* const* d_in, const int* in_sizes, int n_in,
                              void* d_out, int out_size)
{
    const float* x  = (const float*)d_in[0];
    const float* rw = (const float*)d_in[1];
    const float* wg = (const float*)d_in[2];
    const float* wu = (const float*)d_in[3];
    const float* wd = (const float*)d_in[4];
    float* out = (float*)d_out;

    cudaMemsetAsync(d_out, 0, (size_t)out_size * sizeof(float));
    init_kernel<<<1, 32>>>();
    router_kernel<<<TT / 8, 256>>>(x, rw);
    scan_aux_kernel<<<1, 32>>>(out, out_size);
    fill_kernel<<<(TT * KK + 255) / 256, 256>>>();

    cudaFuncSetAttribute(moe_mma_kernel,
                         cudaFuncAttributeMaxDynamicSharedMemorySize, EXP_SMEM);
    moe_mma_kernel<<<148, 256, EXP_SMEM>>>(x, wg, wu, wd);
    combine_kernel<<<TT * 64 / 256, 256>>>(out);
}

// round 10
// speedup vs baseline: 3.9381x; 1.1610x over previous
#include <cuda_runtime.h>
#include <math.h>
#include <stdint.h>

#define TT 8192
#define DD 256
#define FF 1024
#define EE 32
#define KK 4
#define TM 128            // tokens per tile (MMA M)
#define FC 64             // ffn chunk
#define NCH (FF / FC)     // 16

// ---------------- scratch globals ----------------
__device__ int   g_counts[EE];
__device__ int   g_offsets[EE + 1];
__device__ float g_probs_sum[EE];
__device__ int   g_as_e[TT * KK];
__device__ int   g_as_pos[TT * KK];
__device__ float g_as_w[TT * KK];
__device__ int   g_list_tok[TT * KK];
__device__ float g_list_w[TT * KK];
__device__ int   g_slot[TT * KK];
__device__ int   g_tile_e[2048];
__device__ int   g_tile_m0[2048];
__device__ int   g_ntiles;
__device__ float g_scratch[(size_t)TT * KK * DD];   // 32 MB partials

// ---------------- PTX helpers ----------------
__device__ __forceinline__ uint32_t f2tf(float f) {
    uint32_t u;
    asm("cvt.rna.tf32.f32 %0, %1;" : "=r"(u) : "f"(f));
    return u;
}
__device__ __forceinline__ uint32_t f2tf_u(uint32_t bits) {
    uint32_t u;
    asm("cvt.rna.tf32.f32 %0, %1;" : "=r"(u) : "f"(__uint_as_float(bits)));
    return u;
}
__device__ __forceinline__ void mma8(float* c, const uint32_t* a, uint32_t b0, uint32_t b1) {
    asm("mma.sync.aligned.m16n8k8.row.col.f32.tf32.tf32.f32 "
        "{%0,%1,%2,%3},{%4,%5,%6,%7},{%8,%9},{%0,%1,%2,%3};"
        : "+f"(c[0]), "+f"(c[1]), "+f"(c[2]), "+f"(c[3])
        : "r"(a[0]), "r"(a[1]), "r"(a[2]), "r"(a[3]), "r"(b0), "r"(b1));
}
__device__ __forceinline__ void ldm4(uint32_t* r, uint32_t addr) {
    asm volatile("ldmatrix.sync.aligned.m8n8.x4.shared.b16 {%0,%1,%2,%3}, [%4];"
        : "=r"(r[0]), "=r"(r[1]), "=r"(r[2]), "=r"(r[3]) : "r"(addr));
}
__device__ __forceinline__ void cp16(uint32_t dst, const void* src) {
    asm volatile("cp.async.cg.shared.global [%0], [%1], 16;" :: "r"(dst), "l"(src));
}
#define CP_COMMIT() asm volatile("cp.async.commit_group;" ::: "memory")
#define CP_WAIT0()  asm volatile("cp.async.wait_group 0;" ::: "memory")
#define CP_WAIT1()  asm volatile("cp.async.wait_group 1;" ::: "memory")

__device__ __forceinline__ uint32_t smem_u32(const void* p) {
    uint32_t a;
    asm("{ .reg .u64 t; cvta.to.shared.u64 t, %1; cvt.u32.u64 %0, t; }" : "=r"(a) : "l"(p));
    return a;
}

// FFMA-only sigmoid (no MUFU)
__device__ __forceinline__ float fast_sigmoid(float x) {
    float t = -1.442695041f * x;
    float fn = rintf(t);
    int   n  = (int)fn;
    float f  = t - fn;
    float p = 0.0013333558f;
    p = fmaf(p, f, 0.0096181291f);
    p = fmaf(p, f, 0.0555041087f);
    p = fmaf(p, f, 0.2402265069f);
    p = fmaf(p, f, 0.6931471806f);
    p = fmaf(p, f, 1.0f);
    float e = __int_as_float(__float_as_int(p) + (n << 23));
    float d = 1.0f + e;
    float r = __int_as_float(0x7EF311C3 - __float_as_int(d));
    r = r * (2.0f - d * r);
    r = r * (2.0f - d * r);
    r = r * (2.0f - d * r);
    return r;
}

// ---------------- init ----------------
__global__ void init_kernel()
{
    int i = threadIdx.x;
    if (i < EE) { g_counts[i] = 0; g_probs_sum[i] = 0.f; }
}

// ---------------- router (known-good) ----------------
__global__ __launch_bounds__(256) void router_kernel(const float* __restrict__ x,
                                                     const float* __restrict__ rw)
{
    __shared__ float rw_s[EE * 257];
    __shared__ float xsh[8 * 260];
    __shared__ float pacc[EE];

    const int tid  = threadIdx.x;
    const int lane = tid & 31;
    const int warp = tid >> 5;

    for (int i = tid; i < EE * DD; i += 256) {
        int e = i >> 8, d = i & 255;
        rw_s[e * 257 + d] = rw[i];
    }
    if (tid < EE) pacc[tid] = 0.f;
    __syncthreads();

    const int t = blockIdx.x * 8 + warp;
    {
        const float4* xr = (const float4*)(x + (size_t)t * DD);
        float4 a = xr[lane * 2];
        float4 b = xr[lane * 2 + 1];
        *(float4*)&xsh[warp * 260 + lane * 8]     = a;
        *(float4*)&xsh[warp * 260 + lane * 8 + 4] = b;
    }
    __syncwarp();

    float acc = 0.f;
    const float* xrow  = &xsh[warp * 260];
    const float* rwrow = &rw_s[lane * 257];
#pragma unroll 8
    for (int d = 0; d < DD; d++) acc = fmaf(xrow[d], rwrow[d], acc);
    const float logit = acc;

    float m = logit;
#pragma unroll
    for (int o = 16; o; o >>= 1) m = fmaxf(m, __shfl_xor_sync(0xffffffffu, m, o));
    float p = expf(logit - m);
    float s = p;
#pragma unroll
    for (int o = 16; o; o >>= 1) s += __shfl_xor_sync(0xffffffffu, s, o);
    atomicAdd(&pacc[lane], p / s);

    float lv = logit;
    float vals[KK]; int idxs[KK];
#pragma unroll
    for (int k = 0; k < KK; k++) {
        float v = lv; int id = lane;
#pragma unroll
        for (int o = 16; o; o >>= 1) {
            float v2 = __shfl_xor_sync(0xffffffffu, v, o);
            int   i2 = __shfl_xor_sync(0xffffffffu, id, o);
            if (v2 > v || (v2 == v && i2 < id)) { v = v2; id = i2; }
        }
        vals[k] = v; idxs[k] = id;
        if (lane == id) lv = __int_as_float(0xff800000);
    }

    float ws[KK]; float sum = 0.f;
#pragma unroll
    for (int k = 0; k < KK; k++) { ws[k] = expf(vals[k] - vals[0]); sum += ws[k]; }
    const float inv = 1.f / sum;

    if (lane == 0) {
#pragma unroll
        for (int k = 0; k < KK; k++) {
            int e   = idxs[k];
            int pos = atomicAdd(&g_counts[e], 1);
            int a   = t * KK + k;
            g_as_e[a] = e; g_as_pos[a] = pos; g_as_w[a] = ws[k] * inv;
        }
    }
    __syncthreads();
    if (tid < EE) atomicAdd(&g_probs_sum[tid], pacc[tid]);
}

// ---------------- scan offsets + aux loss + tile list ----------------
__global__ void scan_aux_kernel(float* __restrict__ out, int out_size)
{
    const int tid = threadIdx.x;   // 32 threads
    int c = g_counts[tid];
    int v = c;
#pragma unroll
    for (int o = 1; o < 32; o <<= 1) {
        int n = __shfl_up_sync(0xffffffffu, v, o);
        if (tid >= o) v += n;
    }
    g_offsets[tid] = v - c;
    if (tid == 31) g_offsets[EE] = v;

    int nt = (c + TM - 1) / TM;
    int tv = nt;
#pragma unroll
    for (int o = 1; o < 32; o <<= 1) {
        int n = __shfl_up_sync(0xffffffffu, tv, o);
        if (tid >= o) tv += n;
    }
    int tb = tv - nt;
    for (int j = 0; j < nt; j++) { g_tile_e[tb + j] = tid; g_tile_m0[tb + j] = j * TM; }
    if (tid == 31) g_ntiles = tv;

    const float invT = 1.f / (float)TT;
    float part = ((float)c * invT) * (g_probs_sum[tid] * invT);
#pragma unroll
    for (int o = 16; o; o >>= 1) part += __shfl_xor_sync(0xffffffffu, part, o);
    if (tid == 0 && out_size > TT * DD) out[(size_t)TT * DD] = (float)EE * part;
}

// ---------------- per-expert token lists + slot map ----------------
__global__ void fill_kernel()
{
    int i = blockIdx.x * blockDim.x + threadIdx.x;
    if (i < TT * KK) {
        int e    = g_as_e[i];
        int slot = g_offsets[e] + g_as_pos[i];
        g_list_tok[slot] = i >> 2;
        g_list_w[slot]   = g_as_w[i];
        g_slot[i]        = slot;
    }
}

// ---------------- mma.sync tf32 fused expert FFN (fused G+U, ldmatrix) ----------------
// SMEM layout (float offsets):
//   Xs  [128][260]              @ 0       (33280 f)
//   hS  [128][68]               @ 33280   (8704 f)
//   WSU union                   @ 41984   (9216 f)
//     Phase A: [2 buf][2 mat][64 f][36]   (buf stride 4608, mat stride 2304)
//     Phase B: [2 buf][64 d][68]          (buf stride 4352)
//   toks[128] @ 51200, wsh[128] @ 51328
constexpr int OFF_H   = 33280;
constexpr int OFF_WSU = 41984;
constexpr int OFF_TOK = 51200;
constexpr int OFF_WSH = 51328;
constexpr int EXP_SMEM = 51456 * 4;   // 205824 B

__global__ __launch_bounds__(256, 1)
void moe_mma_kernel(const float* __restrict__ x,
                    const float* __restrict__ w_gate,
                    const float* __restrict__ w_up,
                    const float* __restrict__ w_down)
{
    extern __shared__ float sm[];
    float* Xs  = sm;
    float* hS  = sm + OFF_H;
    int*   toks = (int*)(sm + OFF_TOK);
    float* wsh  = sm + OFF_WSH;

    const uint32_t xs_b  = smem_u32(Xs);
    const uint32_t hs_b  = smem_u32(hS);
    const uint32_t wsu_b = smem_u32(sm + OFF_WSU);

    const int tid  = threadIdx.x;
    const int lane = tid & 31;
    const int warp = tid >> 5;
    const int lq   = lane & 3;
    const int lh   = lane >> 2;
    const int wm   = warp & 3;        // M tile (32 rows each)
    const int wn   = warp >> 2;       // N tile (32 cols each)

    // ldmatrix lane-address components
    const int l7  = lane & 7;
    const int l8  = (lane >> 3) & 1;
    const int l16 = (lane >> 4) & 1;

    // A fragments from Xs: rows wm*32 + mt*16 + l7 + 8*l8, col halves by l16
    const uint32_t aA = xs_b + (uint32_t)(((wm * 32 + l7 + 8 * l8) * 260 + l16 * 4) * 4);
    // B fragments (Phase A) from WSU: rows wn*32 + np*16 + l7 + 8*l16, col half by l8
    const uint32_t bA = (uint32_t)(((wn * 32 + l7 + 8 * l16) * 36 + l8 * 4) * 4);
    // A fragments (Phase B) from hS
    const uint32_t hA = hs_b + (uint32_t)(((wm * 32 + l7 + 8 * l8) * 68 + l16 * 4) * 4);
    // B fragments (Phase B) from WSU (Wd layout)
    const uint32_t dA = (uint32_t)(((wn * 32 + l7 + 8 * l16) * 68 + l8 * 4) * 4);

    const int ntiles = g_ntiles;

    for (int tile = blockIdx.x; tile < ntiles; tile += gridDim.x) {
        const int e     = g_tile_e[tile];
        const int m0    = g_tile_m0[tile];
        const int base  = g_offsets[e];
        const int count = g_offsets[e + 1] - base;

        if (tid < TM) {
            int r = m0 + tid;
            bool v = r < count;
            toks[tid] = v ? g_list_tok[base + r] : -1;
            wsh[tid]  = v ? g_list_w[base + r] : 0.f;
        }
        __syncthreads();

        // ---- stage X (tf32-rounded) ----
#pragma unroll 8
        for (int j = 0; j < 32; j++) {
            int idx = tid + j * 256;
            int r = idx >> 6, c4 = (idx & 63) * 4;
            int t = toks[r];
            float4 v = make_float4(0.f, 0.f, 0.f, 0.f);
            if (t >= 0) v = *(const float4*)(x + (size_t)t * DD + c4);
            float4 w;
            w.x = __uint_as_float(f2tf(v.x));
            w.y = __uint_as_float(f2tf(v.y));
            w.z = __uint_as_float(f2tf(v.z));
            w.w = __uint_as_float(f2tf(v.w));
            *(float4*)&Xs[r * 260 + c4] = w;
        }

        const float* wg_e = w_gate + (size_t)e * FF * DD;
        const float* wu_e = w_up   + (size_t)e * FF * DD;
        const float* wd_e = w_down + (size_t)e * DD * FF;

        float acc[4][2][4][4];
#pragma unroll
        for (int q = 0; q < 4; q++)
#pragma unroll
            for (int mt = 0; mt < 2; mt++)
#pragma unroll
                for (int nt = 0; nt < 4; nt++)
#pragma unroll
                    for (int r = 0; r < 4; r++) acc[q][mt][nt][r] = 0.f;

        __syncthreads();   // X visible; WSU free

        for (int c = 0; c < NCH; c++) {
            const int f0 = c * FC;

            // ======== Phase A (fused G+U): cG/cU = X @ {Wg,Wu}^T ========
            float cG[2][4][4], cU[2][4][4];
#pragma unroll
            for (int mt = 0; mt < 2; mt++)
#pragma unroll
                for (int nt = 0; nt < 4; nt++)
#pragma unroll
                    for (int r = 0; r < 4; r++) { cG[mt][nt][r] = 0.f; cU[mt][nt][r] = 0.f; }

            // prologue: slice 0 -> buf 0  (WS layout: [buf][mat][f 64][36])
            {
#pragma unroll
                for (int j = 0; j < 4; j++) {
                    int idx = tid + j * 256;         // 0..1023
                    int mat = idx >> 9;
                    int rem = idx & 511;
                    int f = rem >> 3, d4 = rem & 7;
                    const float* src = (mat ? wu_e : wg_e) + (size_t)(f0 + f) * DD + d4 * 4;
                    cp16(wsu_b + (uint32_t)((mat * 2304 + f * 36) * 4 + d4 * 16), src);
                }
                CP_COMMIT();
            }
#pragma unroll 1
            for (int ks = 0; ks < 8; ks++) {
                if (ks < 7) {
                    int d0n = (ks + 1) * 32;
                    uint32_t bb = wsu_b + (uint32_t)(((ks + 1) & 1) * 4608 * 4);
#pragma unroll
                    for (int j = 0; j < 4; j++) {
                        int idx = tid + j * 256;
                        int mat = idx >> 9;
                        int rem = idx & 511;
                        int f = rem >> 3, d4 = rem & 7;
                        const float* src = (mat ? wu_e : wg_e) + (size_t)(f0 + f) * DD + d0n + d4 * 4;
                        cp16(bb + (uint32_t)((mat * 2304 + f * 36) * 4 + d4 * 16), src);
                    }
                    CP_COMMIT();
                    CP_WAIT1();
                } else {
                    CP_WAIT0();
                }
                __syncthreads();
                const uint32_t wsbB = wsu_b + (uint32_t)((ks & 1) * 4608 * 4);
                const int d0 = ks * 32;
#pragma unroll
                for (int kk = 0; kk < 4; kk++) {
                    uint32_t a[2][4];
#pragma unroll
                    for (int mt = 0; mt < 2; mt++)
                        ldm4(a[mt], aA + (uint32_t)((mt * 16 * 260 + d0 + kk * 8) * 4));
                    uint32_t bg[8], bu[8];
#pragma unroll
                    for (int np = 0; np < 2; np++) {
                        ldm4(bg + np * 4, wsbB + bA + (uint32_t)((np * 16 * 36 + kk * 8) * 4));
                        ldm4(bu + np * 4, wsbB + bA + (uint32_t)((2304 + np * 16 * 36 + kk * 8) * 4));
                    }
#pragma unroll
                    for (int i = 0; i < 8; i++) { bg[i] = f2tf_u(bg[i]); bu[i] = f2tf_u(bu[i]); }
#pragma unroll
                    for (int mt = 0; mt < 2; mt++)
#pragma unroll
                        for (int nt = 0; nt < 4; nt++) {
                            int bi = (nt >> 1) * 4 + (nt & 1) * 2;
                            mma8(cG[mt][nt], a[mt], bg[bi], bg[bi + 1]);
                            mma8(cU[mt][nt], a[mt], bu[bi], bu[bi + 1]);
                        }
                }
                __syncthreads();
            }

            // Phase B prologue: Wd quarter 0 -> union buf 0 (overlaps silu below)
            {
#pragma unroll
                for (int j = 0; j < 4; j++) {
                    int idx = tid + j * 256;
                    int d = idx >> 4, f4 = idx & 15;
                    cp16(wsu_b + (uint32_t)((d * 68) * 4 + f4 * 16),
                         wd_e + (size_t)d * FF + f0 + f4 * 4);
                }
                CP_COMMIT();
            }

            // ---- h = silu(G) * U (tf32-rounded) -> hS ----
#pragma unroll
            for (int mt = 0; mt < 2; mt++)
#pragma unroll
                for (int nt = 0; nt < 4; nt++) {
                    int col = wn * 32 + nt * 8 + 2 * lq;
#pragma unroll
                    for (int hf = 0; hf < 2; hf++) {
                        int row = wm * 32 + mt * 16 + hf * 8 + lh;
                        float g0 = cG[mt][nt][hf * 2 + 0];
                        float g1 = cG[mt][nt][hf * 2 + 1];
                        float h0 = g0 * fast_sigmoid(g0) * cU[mt][nt][hf * 2 + 0];
                        float h1 = g1 * fast_sigmoid(g1) * cU[mt][nt][hf * 2 + 1];
                        float2 o2;
                        o2.x = __uint_as_float(f2tf(h0));
                        o2.y = __uint_as_float(f2tf(h1));
                        *(float2*)&hS[row * 68 + col] = o2;
                    }
                }

            // ======== Phase B: out += h @ Wd^T (4 quarters of D) ========
#pragma unroll 1
            for (int q = 0; q < 4; q++) {
                if (q < 3) {
                    uint32_t bb = wsu_b + (uint32_t)(((q + 1) & 1) * 4352 * 4);
                    int dbase = (q + 1) * 64;
#pragma unroll
                    for (int j = 0; j < 4; j++) {
                        int idx = tid + j * 256;
                        int d = idx >> 4, f4 = idx & 15;
                        cp16(bb + (uint32_t)((d * 68) * 4 + f4 * 16),
                             wd_e + (size_t)(dbase + d) * FF + f0 + f4 * 4);
                    }
                    CP_COMMIT();
                    CP_WAIT1();
                } else {
                    CP_WAIT0();
                }
                __syncthreads();   // cp visible + (q==0) hS stores visible
                const uint32_t wdbB = wsu_b + (uint32_t)((q & 1) * 4352 * 4);
#pragma unroll
                for (int kk = 0; kk < 8; kk++) {
                    uint32_t a[2][4];
#pragma unroll
                    for (int mt = 0; mt < 2; mt++)
                        ldm4(a[mt], hA + (uint32_t)((mt * 16 * 68 + kk * 8) * 4));
                    uint32_t bbr[8];
#pragma unroll
                    for (int np = 0; np < 2; np++)
                        ldm4(bbr + np * 4, wdbB + dA + (uint32_t)((np * 16 * 68 + kk * 8) * 4));
#pragma unroll
                    for (int i = 0; i < 8; i++) bbr[i] = f2tf_u(bbr[i]);
#pragma unroll
                    for (int mt = 0; mt < 2; mt++)
#pragma unroll
                        for (int nt = 0; nt < 4; nt++) {
                            int bi = (nt >> 1) * 4 + (nt & 1) * 2;
                            mma8(acc[q][mt][nt], a[mt], bbr[bi], bbr[bi + 1]);
                        }
                }
                __syncthreads();
            }
        }

        // ---- epilogue: weighted write to scratch ----
#pragma unroll
        for (int q = 0; q < 4; q++)
#pragma unroll
            for (int mt = 0; mt < 2; mt++)
#pragma unroll
                for (int hf = 0; hf < 2; hf++) {
                    int tr = wm * 32 + mt * 16 + hf * 8 + lh;
                    if (m0 + tr < count) {
                        float w = wsh[tr];
                        float* dst = g_scratch + (size_t)(base + m0 + tr) * DD
                                   + q * 64 + wn * 32 + 2 * lq;
#pragma unroll
                        for (int nt = 0; nt < 4; nt++) {
                            float2 v;
                            v.x = acc[q][mt][nt][hf * 2 + 0] * w;
                            v.y = acc[q][mt][nt][hf * 2 + 1] * w;
                            *(float2*)(dst + nt * 8) = v;
                        }
                    }
                }
        __syncthreads();   // protect toks/wsh/Xs before next tile
    }
}

// ---------------- combine: out[t] = sum of token's 4 weighted slots ----------------
__global__ __launch_bounds__(256) void combine_kernel(float* __restrict__ out)
{
    int idx = blockIdx.x * 256 + threadIdx.x;     // TT*64 float4 items
    int t = idx >> 6, q = (idx & 63) * 4;
    const int* sl = g_slot + t * 4;
    float4 a = *(const float4*)(g_scratch + (size_t)sl[0] * DD + q);
    float4 b = *(const float4*)(g_scratch + (size_t)sl[1] * DD + q);
    float4 c = *(const float4*)(g_scratch + (size_t)sl[2] * DD + q);
    float4 d = *(const float4*)(g_scratch + (size_t)sl[3] * DD + q);
    float4 r;
    r.x = a.x + b.x + c.x + d.x;
    r.y = a.y + b.y + c.y + d.y;
    r.z = a.z + b.z + c.z + d.z;
    r.w = a.w + b.w + c.w + d.w;
    *(float4*)(out + (size_t)t * DD + q) = r;
}

// ---------------- launch ----------------
extern "C" void kernel_launch(void* const* d_in, const int* in_sizes, int n_in,
                              void* d_out, int out_size)
{
    const float* x  = (const float*)d_in[0];
    const float* rw = (const float*)d_in[1];
    const float* wg = (const float*)d_in[2];
    const float* wu = (const float*)d_in[3];
    const float* wd = (const float*)d_in[4];
    float* out = (float*)d_out;

    cudaMemsetAsync(d_out, 0, (size_t)out_size * sizeof(float));
    init_kernel<<<1, 32>>>();
    router_kernel<<<TT / 8, 256>>>(x, rw);
    scan_aux_kernel<<<1, 32>>>(out, out_size);
    fill_kernel<<<(TT * KK + 255) / 256, 256>>>();

    cudaFuncSetAttribute(moe_mma_kernel,
                         cudaFuncAttributeMaxDynamicSharedMemorySize, EXP_SMEM);
    moe_mma_kernel<<<148, 256, EXP_SMEM>>>(x, wg, wu, wd);
    combine_kernel<<<TT * 64 / 256, 256>>>(out);
}

// round 11
// speedup vs baseline: 6.0427x; 1.5344x over previous
#include <cuda_runtime.h>
#include <cuda_fp16.h>
#include <math.h>
#include <stdint.h>

#define TT 8192
#define DD 256
#define FF 1024
#define EE 32
#define KK 4
#define TM 128            // tokens per tile (MMA M)
#define FC 64             // ffn chunk
#define NCH (FF / FC)     // 16

// ---------------- scratch globals ----------------
__device__ int   g_counts[EE];
__device__ int   g_offsets[EE + 1];
__device__ float g_probs_sum[EE];
__device__ int   g_as_e[TT * KK];
__device__ int   g_as_pos[TT * KK];
__device__ float g_as_w[TT * KK];
__device__ int   g_list_tok[TT * KK];
__device__ float g_list_w[TT * KK];
__device__ int   g_slot[TT * KK];
__device__ int   g_tile_e[2048];
__device__ int   g_tile_m0[2048];
__device__ int   g_ntiles;
__device__ float g_scratch[(size_t)TT * KK * DD];          // 32 MB partials
__device__ __half g_xh[(size_t)TT * DD];                   // 4 MB fp16 x
__device__ __half g_wh[3][(size_t)EE * FF * DD];           // fp16 wg/wu/wd (16.8 MB each)

// ---------------- PTX helpers ----------------
__device__ __forceinline__ void mma16(float* c, const uint32_t* a, uint32_t b0, uint32_t b1) {
    asm("mma.sync.aligned.m16n8k16.row.col.f32.f16.f16.f32 "
        "{%0,%1,%2,%3},{%4,%5,%6,%7},{%8,%9},{%0,%1,%2,%3};"
        : "+f"(c[0]), "+f"(c[1]), "+f"(c[2]), "+f"(c[3])
        : "r"(a[0]), "r"(a[1]), "r"(a[2]), "r"(a[3]), "r"(b0), "r"(b1));
}
__device__ __forceinline__ void ldm4(uint32_t* r, uint32_t addr) {
    asm volatile("ldmatrix.sync.aligned.m8n8.x4.shared.b16 {%0,%1,%2,%3}, [%4];"
        : "=r"(r[0]), "=r"(r[1]), "=r"(r[2]), "=r"(r[3]) : "r"(addr));
}
__device__ __forceinline__ void cp16(uint32_t dst, const void* src) {
    asm volatile("cp.async.cg.shared.global [%0], [%1], 16;" :: "r"(dst), "l"(src));
}
__device__ __forceinline__ void cp16z(uint32_t dst, const void* src, int ssz) {
    asm volatile("cp.async.cg.shared.global [%0], [%1], 16, %2;" :: "r"(dst), "l"(src), "r"(ssz));
}
#define CP_COMMIT() asm volatile("cp.async.commit_group;" ::: "memory")
#define CP_WAIT0()  asm volatile("cp.async.wait_group 0;" ::: "memory")
#define CP_WAIT1()  asm volatile("cp.async.wait_group 1;" ::: "memory")

__device__ __forceinline__ uint32_t smem_u32(const void* p) {
    uint32_t a;
    asm("{ .reg .u64 t; cvta.to.shared.u64 t, %1; cvt.u32.u64 %0, t; }" : "=r"(a) : "l"(p));
    return a;
}

// FFMA-only sigmoid (no MUFU)
__device__ __forceinline__ float fast_sigmoid(float x) {
    float t = -1.442695041f * x;
    float fn = rintf(t);
    int   n  = (int)fn;
    float f  = t - fn;
    float p = 0.0013333558f;
    p = fmaf(p, f, 0.0096181291f);
    p = fmaf(p, f, 0.0555041087f);
    p = fmaf(p, f, 0.2402265069f);
    p = fmaf(p, f, 0.6931471806f);
    p = fmaf(p, f, 1.0f);
    float e = __int_as_float(__float_as_int(p) + (n << 23));
    float d = 1.0f + e;
    float r = __int_as_float(0x7EF311C3 - __float_as_int(d));
    r = r * (2.0f - d * r);
    r = r * (2.0f - d * r);
    r = r * (2.0f - d * r);
    return r;
}

// ---------------- init ----------------
__global__ void init_kernel()
{
    int i = threadIdx.x;
    if (i < EE) { g_counts[i] = 0; g_probs_sum[i] = 0.f; }
}

// ---------------- fp32 -> fp16 conversion (8 elems/thread) ----------------
__global__ __launch_bounds__(256) void conv_kernel(const float* __restrict__ src,
                                                   int which, int n8)
{
    int i = blockIdx.x * 256 + threadIdx.x;
    if (i >= n8) return;
    __half* dst = (which == 0) ? g_xh : g_wh[which - 1];
    float4 a = ((const float4*)src)[2 * i];
    float4 b = ((const float4*)src)[2 * i + 1];
    __half2 h0 = __floats2half2_rn(a.x, a.y);
    __half2 h1 = __floats2half2_rn(a.z, a.w);
    __half2 h2 = __floats2half2_rn(b.x, b.y);
    __half2 h3 = __floats2half2_rn(b.z, b.w);
    uint4 o;
    o.x = *(uint32_t*)&h0; o.y = *(uint32_t*)&h1;
    o.z = *(uint32_t*)&h2; o.w = *(uint32_t*)&h3;
    ((uint4*)dst)[i] = o;
}

// ---------------- router (known-good) ----------------
__global__ __launch_bounds__(256) void router_kernel(const float* __restrict__ x,
                                                     const float* __restrict__ rw)
{
    __shared__ float rw_s[EE * 257];
    __shared__ float xsh[8 * 260];
    __shared__ float pacc[EE];

    const int tid  = threadIdx.x;
    const int lane = tid & 31;
    const int warp = tid >> 5;

    for (int i = tid; i < EE * DD; i += 256) {
        int e = i >> 8, d = i & 255;
        rw_s[e * 257 + d] = rw[i];
    }
    if (tid < EE) pacc[tid] = 0.f;
    __syncthreads();

    const int t = blockIdx.x * 8 + warp;
    {
        const float4* xr = (const float4*)(x + (size_t)t * DD);
        float4 a = xr[lane * 2];
        float4 b = xr[lane * 2 + 1];
        *(float4*)&xsh[warp * 260 + lane * 8]     = a;
        *(float4*)&xsh[warp * 260 + lane * 8 + 4] = b;
    }
    __syncwarp();

    float acc = 0.f;
    const float* xrow  = &xsh[warp * 260];
    const float* rwrow = &rw_s[lane * 257];
#pragma unroll 8
    for (int d = 0; d < DD; d++) acc = fmaf(xrow[d], rwrow[d], acc);
    const float logit = acc;

    float m = logit;
#pragma unroll
    for (int o = 16; o; o >>= 1) m = fmaxf(m, __shfl_xor_sync(0xffffffffu, m, o));
    float p = expf(logit - m);
    float s = p;
#pragma unroll
    for (int o = 16; o; o >>= 1) s += __shfl_xor_sync(0xffffffffu, s, o);
    atomicAdd(&pacc[lane], p / s);

    float lv = logit;
    float vals[KK]; int idxs[KK];
#pragma unroll
    for (int k = 0; k < KK; k++) {
        float v = lv; int id = lane;
#pragma unroll
        for (int o = 16; o; o >>= 1) {
            float v2 = __shfl_xor_sync(0xffffffffu, v, o);
            int   i2 = __shfl_xor_sync(0xffffffffu, id, o);
            if (v2 > v || (v2 == v && i2 < id)) { v = v2; id = i2; }
        }
        vals[k] = v; idxs[k] = id;
        if (lane == id) lv = __int_as_float(0xff800000);
    }

    float ws[KK]; float sum = 0.f;
#pragma unroll
    for (int k = 0; k < KK; k++) { ws[k] = expf(vals[k] - vals[0]); sum += ws[k]; }
    const float inv = 1.f / sum;

    if (lane == 0) {
#pragma unroll
        for (int k = 0; k < KK; k++) {
            int e   = idxs[k];
            int pos = atomicAdd(&g_counts[e], 1);
            int a   = t * KK + k;
            g_as_e[a] = e; g_as_pos[a] = pos; g_as_w[a] = ws[k] * inv;
        }
    }
    __syncthreads();
    if (tid < EE) atomicAdd(&g_probs_sum[tid], pacc[tid]);
}

// ---------------- scan offsets + aux loss + tile list ----------------
__global__ void scan_aux_kernel(float* __restrict__ out, int out_size)
{
    const int tid = threadIdx.x;   // 32 threads
    int c = g_counts[tid];
    int v = c;
#pragma unroll
    for (int o = 1; o < 32; o <<= 1) {
        int n = __shfl_up_sync(0xffffffffu, v, o);
        if (tid >= o) v += n;
    }
    g_offsets[tid] = v - c;
    if (tid == 31) g_offsets[EE] = v;

    int nt = (c + TM - 1) / TM;
    int tv = nt;
#pragma unroll
    for (int o = 1; o < 32; o <<= 1) {
        int n = __shfl_up_sync(0xffffffffu, tv, o);
        if (tid >= o) tv += n;
    }
    int tb = tv - nt;
    for (int j = 0; j < nt; j++) { g_tile_e[tb + j] = tid; g_tile_m0[tb + j] = j * TM; }
    if (tid == 31) g_ntiles = tv;

    const float invT = 1.f / (float)TT;
    float part = ((float)c * invT) * (g_probs_sum[tid] * invT);
#pragma unroll
    for (int o = 16; o; o >>= 1) part += __shfl_xor_sync(0xffffffffu, part, o);
    if (tid == 0 && out_size > TT * DD) out[(size_t)TT * DD] = (float)EE * part;
}

// ---------------- per-expert token lists + slot map ----------------
__global__ void fill_kernel()
{
    int i = blockIdx.x * blockDim.x + threadIdx.x;
    if (i < TT * KK) {
        int e    = g_as_e[i];
        int slot = g_offsets[e] + g_as_pos[i];
        g_list_tok[slot] = i >> 2;
        g_list_w[slot]   = g_as_w[i];
        g_slot[i]        = slot;
    }
}

// ---------------- fp16 mma.sync fused expert FFN ----------------
// SMEM layout (halves):
//   Xs  [128][264]            @ 0       (33792 h)  row stride 264 (528B, bank-offset 4)
//   hS  [128][72]             @ 33792   (9216 h)   row stride 72 (144B, bank-offset 4)
//   WSU union                 @ 43008   (18432 h)
//     Phase A: [2 buf][2 mat][64 f][72]  buf stride 9216, mat stride 4608
//     Phase B: [2 buf][64 d][72]         buf stride 4608
//   toks[128] ints @ 61440h, wsh[128] floats after
constexpr int XS_STRIDE = 264;
constexpr int HS_STRIDE = 72;
constexpr int OFF_H    = 33792;
constexpr int OFF_WSU  = 43008;
constexpr int OFF_MISC = 61440;                 // halves
constexpr int EXP_SMEM = OFF_MISC * 2 + 1024;   // 123904 B

__global__ __launch_bounds__(256, 1)
void moe_mma_kernel()
{
    extern __shared__ __half sm[];
    __half* Xs = sm;
    __half* hS = sm + OFF_H;
    int*   toks = (int*)(sm + OFF_MISC);
    float* wsh  = (float*)(toks + 128);

    const uint32_t xs_b  = smem_u32(Xs);
    const uint32_t hs_b  = smem_u32(hS);
    const uint32_t wsu_b = smem_u32(sm + OFF_WSU);

    const int tid  = threadIdx.x;
    const int lane = tid & 31;
    const int warp = tid >> 5;
    const int lq   = lane & 3;
    const int lh   = lane >> 2;
    const int wm   = warp & 3;        // M tile (32 rows each)
    const int wn   = warp >> 2;       // N tile (32 cols each)

    const int l7  = lane & 7;
    const int l8  = (lane >> 3) & 1;
    const int l16 = (lane >> 4) & 1;

    const int rowA0 = wm * 32 + l7 + 8 * l8;    // + mt*16
    const int rowB0 = wn * 32 + l7 + 8 * l8;    // + nt2*16

    const uint32_t aX = xs_b + (uint32_t)((rowA0 * XS_STRIDE + l16 * 8) * 2);
    const uint32_t aH = hs_b + (uint32_t)((rowA0 * HS_STRIDE + l16 * 8) * 2);
    const uint32_t bW = (uint32_t)((rowB0 * HS_STRIDE + l16 * 8) * 2);   // rel to W region

    const int ntiles = g_ntiles;

    for (int tile = blockIdx.x; tile < ntiles; tile += gridDim.x) {
        const int e     = g_tile_e[tile];
        const int m0    = g_tile_m0[tile];
        const int base  = g_offsets[e];
        const int count = g_offsets[e + 1] - base;

        if (tid < TM) {
            int r = m0 + tid;
            bool v = r < count;
            toks[tid] = v ? g_list_tok[base + r] : -1;
            wsh[tid]  = v ? g_list_w[base + r] : 0.f;
        }
        __syncthreads();

        // ---- stage X fp16: 128 rows x 256 halves = 4096 x 16B ----
#pragma unroll 4
        for (int j = 0; j < 16; j++) {
            int idx = tid + j * 256;
            int r = idx >> 5, c8 = idx & 31;
            int t = toks[r];
            uint32_t dst = xs_b + (uint32_t)((r * XS_STRIDE + c8 * 8) * 2);
            const __half* src = g_xh + ((size_t)(t < 0 ? 0 : t) * DD + c8 * 8);
            cp16z(dst, src, t < 0 ? 0 : 16);
        }
        CP_COMMIT();

        const __half* wg_h = g_wh[0] + (size_t)e * FF * DD;
        const __half* wu_h = g_wh[1] + (size_t)e * FF * DD;
        const __half* wd_h = g_wh[2] + (size_t)e * DD * FF;

        float acc[4][2][4][4];
#pragma unroll
        for (int q = 0; q < 4; q++)
#pragma unroll
            for (int mt = 0; mt < 2; mt++)
#pragma unroll
                for (int nt = 0; nt < 4; nt++)
#pragma unroll
                    for (int r = 0; r < 4; r++) acc[q][mt][nt][r] = 0.f;

        CP_WAIT0();
        __syncthreads();   // X visible; WSU free

        for (int c = 0; c < NCH; c++) {
            const int f0 = c * FC;

            // ======== Phase A (fused G+U): 4 k-slices of 64 ========
            float cG[2][4][4], cU[2][4][4];
#pragma unroll
            for (int mt = 0; mt < 2; mt++)
#pragma unroll
                for (int nt = 0; nt < 4; nt++)
#pragma unroll
                    for (int r = 0; r < 4; r++) { cG[mt][nt][r] = 0.f; cU[mt][nt][r] = 0.f; }

            // prologue: slice 0 -> buf 0   (1024 cp16: [mat][f 64][8 chunks])
            {
#pragma unroll
                for (int j = 0; j < 4; j++) {
                    int idx = tid + j * 256;
                    int mat = idx >> 9;
                    int rem = idx & 511;
                    int f = rem >> 3, c8 = rem & 7;
                    const __half* src = (mat ? wu_h : wg_h) + (size_t)(f0 + f) * DD + c8 * 8;
                    cp16(wsu_b + (uint32_t)(((mat * 4608 + f * HS_STRIDE) + c8 * 8) * 2), src);
                }
                CP_COMMIT();
            }
#pragma unroll 1
            for (int ks = 0; ks < 4; ks++) {
                if (ks < 3) {
                    int d0n = (ks + 1) * 64;
                    uint32_t bb = wsu_b + (uint32_t)(((ks + 1) & 1) * 9216 * 2);
#pragma unroll
                    for (int j = 0; j < 4; j++) {
                        int idx = tid + j * 256;
                        int mat = idx >> 9;
                        int rem = idx & 511;
                        int f = rem >> 3, c8 = rem & 7;
                        const __half* src = (mat ? wu_h : wg_h) + (size_t)(f0 + f) * DD + d0n + c8 * 8;
                        cp16(bb + (uint32_t)(((mat * 4608 + f * HS_STRIDE) + c8 * 8) * 2), src);
                    }
                    CP_COMMIT();
                    CP_WAIT1();
                } else {
                    CP_WAIT0();
                }
                __syncthreads();
                const uint32_t wsbB = wsu_b + (uint32_t)((ks & 1) * 9216 * 2);
                const int d0 = ks * 64;
#pragma unroll
                for (int kk = 0; kk < 4; kk++) {
                    uint32_t a[2][4];
#pragma unroll
                    for (int mt = 0; mt < 2; mt++)
                        ldm4(a[mt], aX + (uint32_t)(((mt * 16 * XS_STRIDE) + d0 + kk * 16) * 2));
                    uint32_t bg[8], bu[8];
#pragma unroll
                    for (int nt2 = 0; nt2 < 2; nt2++) {
                        ldm4(bg + nt2 * 4, wsbB + bW + (uint32_t)(((nt2 * 16 * HS_STRIDE) + kk * 16) * 2));
                        ldm4(bu + nt2 * 4, wsbB + bW + (uint32_t)(((4608 + nt2 * 16 * HS_STRIDE) + kk * 16) * 2));
                    }
#pragma unroll
                    for (int mt = 0; mt < 2; mt++)
#pragma unroll
                        for (int nt = 0; nt < 4; nt++) {
                            int nt2 = nt >> 1, hi = nt & 1;
                            mma16(cG[mt][nt], a[mt], bg[nt2 * 4 + hi], bg[nt2 * 4 + 2 + hi]);
                            mma16(cU[mt][nt], a[mt], bu[nt2 * 4 + hi], bu[nt2 * 4 + 2 + hi]);
                        }
                }
                __syncthreads();
            }

            // Phase B prologue: Wd quarter 0 -> union buf 0 (overlaps silu)
            {
#pragma unroll
                for (int j = 0; j < 2; j++) {
                    int idx = tid + j * 256;
                    int d = idx >> 3, c8 = idx & 7;
                    cp16(wsu_b + (uint32_t)(((d * HS_STRIDE) + c8 * 8) * 2),
                         wd_h + (size_t)d * FF + f0 + c8 * 8);
                }
                CP_COMMIT();
            }

            // ---- h = silu(G) * U -> hS (fp16) ----
#pragma unroll
            for (int mt = 0; mt < 2; mt++)
#pragma unroll
                for (int nt = 0; nt < 4; nt++) {
                    int col = wn * 32 + nt * 8 + 2 * lq;
#pragma unroll
                    for (int hf = 0; hf < 2; hf++) {
                        int row = wm * 32 + mt * 16 + hf * 8 + lh;
                        float g0 = cG[mt][nt][hf * 2 + 0];
                        float g1 = cG[mt][nt][hf * 2 + 1];
                        float h0 = g0 * fast_sigmoid(g0) * cU[mt][nt][hf * 2 + 0];
                        float h1 = g1 * fast_sigmoid(g1) * cU[mt][nt][hf * 2 + 1];
                        __half2 o2 = __floats2half2_rn(h0, h1);
                        *(__half2*)&hS[row * HS_STRIDE + col] = o2;
                    }
                }

            // ======== Phase B: out += h @ Wd^T (4 quarters of D) ========
#pragma unroll 1
            for (int q = 0; q < 4; q++) {
                if (q < 3) {
                    uint32_t bb = wsu_b + (uint32_t)(((q + 1) & 1) * 4608 * 2);
                    int dbase = (q + 1) * 64;
#pragma unroll
                    for (int j = 0; j < 2; j++) {
                        int idx = tid + j * 256;
                        int d = idx >> 3, c8 = idx & 7;
                        cp16(bb + (uint32_t)(((d * HS_STRIDE) + c8 * 8) * 2),
                             wd_h + (size_t)(dbase + d) * FF + f0 + c8 * 8);
                    }
                    CP_COMMIT();
                    CP_WAIT1();
                } else {
                    CP_WAIT0();
                }
                __syncthreads();   // cp visible + (q==0) hS stores visible
                const uint32_t wdbB = wsu_b + (uint32_t)((q & 1) * 4608 * 2);
#pragma unroll
                for (int kk = 0; kk < 4; kk++) {
                    uint32_t a[2][4];
#pragma unroll
                    for (int mt = 0; mt < 2; mt++)
                        ldm4(a[mt], aH + (uint32_t)(((mt * 16 * HS_STRIDE) + kk * 16) * 2));
                    uint32_t bbr[8];
#pragma unroll
                    for (int nt2 = 0; nt2 < 2; nt2++)
                        ldm4(bbr + nt2 * 4, wdbB + bW + (uint32_t)(((nt2 * 16 * HS_STRIDE) + kk * 16) * 2));
#pragma unroll
                    for (int mt = 0; mt < 2; mt++)
#pragma unroll
                        for (int nt = 0; nt < 4; nt++) {
                            int nt2 = nt >> 1, hi = nt & 1;
                            mma16(acc[q][mt][nt], a[mt], bbr[nt2 * 4 + hi], bbr[nt2 * 4 + 2 + hi]);
                        }
                }
                __syncthreads();
            }
        }

        // ---- epilogue: weighted write to scratch ----
#pragma unroll
        for (int q = 0; q < 4; q++)
#pragma unroll
            for (int mt = 0; mt < 2; mt++)
#pragma unroll
                for (int hf = 0; hf < 2; hf++) {
                    int tr = wm * 32 + mt * 16 + hf * 8 + lh;
                    if (m0 + tr < count) {
                        float w = wsh[tr];
                        float* dst = g_scratch + (size_t)(base + m0 + tr) * DD
                                   + q * 64 + wn * 32 + 2 * lq;
#pragma unroll
                        for (int nt = 0; nt < 4; nt++) {
                            float2 v;
                            v.x = acc[q][mt][nt][hf * 2 + 0] * w;
                            v.y = acc[q][mt][nt][hf * 2 + 1] * w;
                            *(float2*)(dst + nt * 8) = v;
                        }
                    }
                }
        __syncthreads();   // protect toks/wsh/Xs before next tile
    }
}

// ---------------- combine: out[t] = sum of token's 4 weighted slots ----------------
__global__ __launch_bounds__(256) void combine_kernel(float* __restrict__ out)
{
    int idx = blockIdx.x * 256 + threadIdx.x;     // TT*64 float4 items
    int t = idx >> 6, q = (idx & 63) * 4;
    const int* sl = g_slot + t * 4;
    float4 a = *(const float4*)(g_scratch + (size_t)sl[0] * DD + q);
    float4 b = *(const float4*)(g_scratch + (size_t)sl[1] * DD + q);
    float4 c = *(const float4*)(g_scratch + (size_t)sl[2] * DD + q);
    float4 d = *(const float4*)(g_scratch + (size_t)sl[3] * DD + q);
    float4 r;
    r.x = a.x + b.x + c.x + d.x;
    r.y = a.y + b.y + c.y + d.y;
    r.z = a.z + b.z + c.z + d.z;
    r.w = a.w + b.w + c.w + d.w;
    *(float4*)(out + (size_t)t * DD + q) = r;
}

// ---------------- launch ----------------
extern "C" void kernel_launch(void* const* d_in, const int* in_sizes, int n_in,
                              void* d_out, int out_size)
{
    const float* x  = (const float*)d_in[0];
    const float* rw = (const float*)d_in[1];
    const float* wg = (const float*)d_in[2];
    const float* wu = (const float*)d_in[3];
    const float* wd = (const float*)d_in[4];
    float* out = (float*)d_out;

    cudaMemsetAsync(d_out, 0, (size_t)out_size * sizeof(float));
    init_kernel<<<1, 32>>>();
    router_kernel<<<TT / 8, 256>>>(x, rw);
    scan_aux_kernel<<<1, 32>>>(out, out_size);
    fill_kernel<<<(TT * KK + 255) / 256, 256>>>();

    // fp32 -> fp16 conversions
    const int n8x = TT * DD / 8;
    const int n8w = EE * FF * DD / 8;
    conv_kernel<<<(n8x + 255) / 256, 256>>>(x,  0, n8x);
    conv_kernel<<<(n8w + 255) / 256, 256>>>(wg, 1, n8w);
    conv_kernel<<<(n8w + 255) / 256, 256>>>(wu, 2, n8w);
    conv_kernel<<<(n8w + 255) / 256, 256>>>(wd, 3, n8w);

    cudaFuncSetAttribute(moe_mma_kernel,
                         cudaFuncAttributeMaxDynamicSharedMemorySize, EXP_SMEM);
    moe_mma_kernel<<<148, 256, EXP_SMEM>>>();
    combine_kernel<<<TT * 64 / 256, 256>>>(out);
}